// round 13
// baseline (speedup 1.0000x reference)
#include <cuda_runtime.h>

#define E_NUM 32000
#define NODES 1600
#define CCH 128
#define M0C 7
#define NSPH 49
#define NALL 29
#define BASIS 512
#define HID 128
#define DIN 768
#define W3N 896
#define WROW (NSPH*NALL)   /* 1421 */
#define NGATH (NSPH*M0C)   /* 343 */

#define AST 40    /* GEMM A smem row stride (bf16 elems) */
#define BST 136   /* GEMM B smem row stride (bf16 elems) */
#define ASTN 24   /* k_node A (wigner) smem row stride  */
#define BSTN 136  /* k_node B (x0) smem row stride      */

typedef unsigned long long ull;
typedef unsigned int u32;
typedef unsigned short u16;

// ---------------- scratch (device globals: allocation-free) ----------------
__device__ float g_h1[(size_t)E_NUM * HID];
__device__ float g_h2[(size_t)E_NUM * HID];
__device__ u16   g_x0h[(size_t)E_NUM * W3N];
__device__ u16   g_x0l[(size_t)E_NUM * W3N];
__device__ int   g_count[NODES];
__device__ int   g_off[NODES + 1];
__device__ int   g_cursor[NODES];
__device__ int   g_edges[E_NUM];
__device__ int   g_wigidx[NGATH];   // src: r*NALL + pos[m]
__device__ int   g_dstidx[NGATH];   // dst: r*ASTN + m

// ---------------- helpers ----------------
__device__ __forceinline__ u32 smem_u32(const void* p) {
    u32 a;
    asm("{ .reg .u64 t; cvta.to.shared.u64 t, %1; cvt.u32.u64 %0, t; }"
        : "=r"(a) : "l"(p));
    return a;
}

// split pair (a0,a1): hi = packed bf16x2 (a0 in low half), lo = packed residual
__device__ __forceinline__ void split2(float a0, float a1, u32& hi, u32& lo) {
    u32 h;
    asm("cvt.rn.satfinite.bf16x2.f32 %0, %1, %2;" : "=r"(h) : "f"(a1), "f"(a0));
    float hf0 = __uint_as_float(h << 16);
    float hf1 = __uint_as_float(h & 0xffff0000u);
    float l0 = a0 - hf0, l1 = a1 - hf1;
    asm("cvt.rn.satfinite.bf16x2.f32 %0, %1, %2;" : "=r"(lo) : "f"(l1), "f"(l0));
    hi = h;
}
// scalar split
__device__ __forceinline__ void split1(float v, u16& hi, u16& lo) {
    u32 u = __float_as_uint(v);
    u32 hb = (u + 0x7fffu + ((u >> 16) & 1u)) >> 16;
    float hf = __uint_as_float(hb << 16);
    float l = v - hf;
    u32 ul = __float_as_uint(l);
    u32 lb = (ul + 0x7fffu + ((ul >> 16) & 1u)) >> 16;
    hi = (u16)hb; lo = (u16)lb;
}

#define LDSM4(r0,r1,r2,r3,a) \
    asm volatile("ldmatrix.sync.aligned.m8n8.x4.shared.b16 {%0,%1,%2,%3}, [%4];" \
                 : "=r"(r0), "=r"(r1), "=r"(r2), "=r"(r3) : "r"(a))
#define LDSM4T(r0,r1,r2,r3,a) \
    asm volatile("ldmatrix.sync.aligned.m8n8.x4.trans.shared.b16 {%0,%1,%2,%3}, [%4];" \
                 : "=r"(r0), "=r"(r1), "=r"(r2), "=r"(r3) : "r"(a))
#define MMA_BF16(d, a0,a1,a2,a3, b0,b1) \
    asm volatile("mma.sync.aligned.m16n8k16.row.col.f32.bf16.bf16.f32 " \
                 "{%0,%1,%2,%3}, {%4,%5,%6,%7}, {%8,%9}, {%0,%1,%2,%3};" \
                 : "+f"((d)[0]), "+f"((d)[1]), "+f"((d)[2]), "+f"((d)[3]) \
                 : "r"(a0), "r"(a1), "r"(a2), "r"(a3), "r"(b0), "r"(b1))

// ---------------- CSR build ----------------
__global__ void k_zero() {
    int i = blockIdx.x * 256 + threadIdx.x;
    if (i < NODES) { g_count[i] = 0; g_cursor[i] = 0; }
}
__global__ void k_hist(const int* __restrict__ eidx) {
    int e = blockIdx.x * 256 + threadIdx.x;
    if (e < E_NUM) atomicAdd(&g_count[eidx[E_NUM + e]], 1);
}
__global__ void k_prep(const float* __restrict__ tom) {
    __shared__ int csum[256];
    __shared__ int spos[M0C];
    int tid = threadIdx.x;
    if (tid < M0C) {
        int p = 0;
        for (int j = 0; j < NALL; j++)
            if (tom[tid * NALL + j] > 0.5f) p = j;
        spos[tid] = p;
    }
    __syncthreads();
    for (int i = tid; i < NGATH; i += 256) {
        int r = i / M0C;
        int m = i - r * M0C;
        g_wigidx[i] = r * NALL + spos[m];
        g_dstidx[i] = r * ASTN + m;
    }
    int base = tid * 7;
    int s = 0;
    for (int i = 0; i < 7; i++) {
        int idx = base + i;
        if (idx < NODES) s += g_count[idx];
    }
    csum[tid] = s;
    __syncthreads();
    if (tid == 0) {
        int run = 0;
        for (int i = 0; i < 256; i++) { int t = csum[i]; csum[i] = run; run += t; }
        g_off[NODES] = run;
    }
    __syncthreads();
    int run = csum[tid];
    for (int i = 0; i < 7; i++) {
        int idx = base + i;
        if (idx < NODES) { g_off[idx] = run; run += g_count[idx]; }
    }
}
__global__ void k_scatter(const int* __restrict__ eidx) {
    int e = blockIdx.x * 256 + threadIdx.x;
    if (e < E_NUM) {
        int t = eidx[E_NUM + e];
        int p = atomicAdd(&g_cursor[t], 1);
        g_edges[g_off[t] + p] = e;
    }
}

// ---------------- shared MMA machinery ----------------
__device__ __forceinline__ void compute_iter(u32 ahB, u32 alB, u32 bhB, u32 blB,
                                             float acc[2][8][4])
{
#pragma unroll
    for (int ks = 0; ks < 2; ks++) {
        u32 ah[2][4], al[2][4];
#pragma unroll
        for (int mt = 0; mt < 2; mt++) {
            LDSM4(ah[mt][0], ah[mt][1], ah[mt][2], ah[mt][3],
                  ahB + mt * (16 * AST * 2) + ks * 32);
            LDSM4(al[mt][0], al[mt][1], al[mt][2], al[mt][3],
                  alB + mt * (16 * AST * 2) + ks * 32);
        }
        u32 bh[4][4], bl[4][4];
#pragma unroll
        for (int p = 0; p < 4; p++) {
            LDSM4T(bh[p][0], bh[p][1], bh[p][2], bh[p][3],
                   bhB + ks * (16 * BST * 2) + p * 32);
            LDSM4T(bl[p][0], bl[p][1], bl[p][2], bl[p][3],
                   blB + ks * (16 * BST * 2) + p * 32);
        }
#pragma unroll
        for (int mt = 0; mt < 2; mt++)
#pragma unroll
            for (int p = 0; p < 4; p++)
#pragma unroll
                for (int h = 0; h < 2; h++) {
                    int nt = p * 2 + h;
                    MMA_BF16(acc[mt][nt], ah[mt][0], ah[mt][1], ah[mt][2], ah[mt][3],
                             bh[p][h * 2], bh[p][h * 2 + 1]);
                    MMA_BF16(acc[mt][nt], ah[mt][0], ah[mt][1], ah[mt][2], ah[mt][3],
                             bl[p][h * 2], bl[p][h * 2 + 1]);
                    MMA_BF16(acc[mt][nt], al[mt][0], al[mt][1], al[mt][2], al[mt][3],
                             bh[p][h * 2], bh[p][h * 2 + 1]);
                }
    }
}

__device__ __forceinline__ void stage_a16(u16* Ahs, u16* Als, int r, int kh,
                                          const float4* af)
{
#pragma unroll
    for (int j = 0; j < 4; j++) {
        float4 f = af[j];
        u32 h0, l0, h1, l1;
        split2(f.x, f.y, h0, l0);
        split2(f.z, f.w, h1, l1);
        int off = r * AST + kh + j * 4;
        *(u32*)&Ahs[off] = h0; *(u32*)&Ahs[off + 2] = h1;
        *(u32*)&Als[off] = l0; *(u32*)&Als[off + 2] = l1;
    }
}
__device__ __forceinline__ void stage_b16(u16* Bhs, u16* Bls, int bk, int bc,
                                          const float4* bf)
{
#pragma unroll
    for (int j = 0; j < 4; j++) {
        float4 f = bf[j];
        u32 h0, l0, h1, l1;
        split2(f.x, f.y, h0, l0);
        split2(f.z, f.w, h1, l1);
        int off = bk * BST + bc + j * 4;
        *(u32*)&Bhs[off] = h0; *(u32*)&Bhs[off + 2] = h1;
        *(u32*)&Bls[off] = l0; *(u32*)&Bls[off + 2] = l1;
    }
}

// fused bias + LN + SiLU epilogue with cross-warp row reduction, fp32 store
__device__ __forceinline__ void ln_epi_mma(
    float acc[2][8][4], int rowBase, int wr, int wc, int lane,
    const float* __restrict__ bias, const float* __restrict__ gam,
    const float* __restrict__ bet, float* __restrict__ out,
    float* redS, float* redQ)
{
    int gid = lane >> 2, q = lane & 3;
#pragma unroll
    for (int mt = 0; mt < 2; mt++)
#pragma unroll
        for (int sub = 0; sub < 2; sub++) {
            int rl = wr * 32 + mt * 16 + sub * 8 + gid;
            float s = 0.f, s2 = 0.f;
#pragma unroll
            for (int nt = 0; nt < 8; nt++)
#pragma unroll
                for (int e = 0; e < 2; e++) {
                    int col = wc * 64 + nt * 8 + q * 2 + e;
                    float v = acc[mt][nt][sub * 2 + e] + bias[col];
                    acc[mt][nt][sub * 2 + e] = v;
                    s += v; s2 += v * v;
                }
            s  += __shfl_xor_sync(0xffffffffu, s, 1);
            s  += __shfl_xor_sync(0xffffffffu, s, 2);
            s2 += __shfl_xor_sync(0xffffffffu, s2, 1);
            s2 += __shfl_xor_sync(0xffffffffu, s2, 2);
            if (q == 0) { redS[rl * 2 + wc] = s; redQ[rl * 2 + wc] = s2; }
        }
    __syncthreads();
#pragma unroll
    for (int mt = 0; mt < 2; mt++)
#pragma unroll
        for (int sub = 0; sub < 2; sub++) {
            int rl = wr * 32 + mt * 16 + sub * 8 + gid;
            float st = redS[rl * 2] + redS[rl * 2 + 1];
            float st2 = redQ[rl * 2] + redQ[rl * 2 + 1];
            float mean = st * (1.f / 128.f);
            float var = st2 * (1.f / 128.f) - mean * mean;
            float rstd = rsqrtf(var + 1e-5f);
            float* op = out + (size_t)(rowBase + rl) * HID;
#pragma unroll
            for (int nt = 0; nt < 8; nt++) {
                int col = wc * 64 + nt * 8 + q * 2;
                float y0 = (acc[mt][nt][sub * 2] - mean) * rstd * gam[col] + bet[col];
                float y1 = (acc[mt][nt][sub * 2 + 1] - mean) * rstd * gam[col + 1] + bet[col + 1];
                float o0 = y0 / (1.f + __expf(-y0));
                float o1 = y1 / (1.f + __expf(-y1));
                *(float2*)(op + col) = make_float2(o0, o1);
            }
        }
}

// ---------------- GEMM1: gathered [E,768] @ w1 -> LN/SiLU -> g_h1 ----------
__global__ __launch_bounds__(256) void k_mgemm1(
    const int* __restrict__ an, const float* __restrict__ ed,
    const int* __restrict__ eidx, const float* __restrict__ srcT,
    const float* __restrict__ tgtT, const float* __restrict__ w1,
    const float* __restrict__ b1, const float* __restrict__ g1,
    const float* __restrict__ be1)
{
    __shared__ __align__(16) u16 Ahs[128 * AST], Als[128 * AST];
    __shared__ __align__(16) u16 Bhs[32 * BST], Bls[32 * BST];
    __shared__ float redS[128 * 2], redQ[128 * 2];
    const int tid = threadIdx.x, lane = tid & 31, wid = tid >> 5;
    const int wr = wid >> 1, wc = wid & 1;
    const int rowBase = blockIdx.x * 128;

    const int r = tid >> 1, kh = (tid & 1) * 16;
    const int eRow = rowBase + r;
    const float* edRow = ed + (size_t)eRow * BASIS;
    const float* srcRow = srcT + (size_t)an[eidx[eRow]] * HID;
    const float* tgtRow = tgtT + (size_t)an[eidx[E_NUM + eRow]] * HID;
    const int bk = tid >> 3, bc = (tid & 7) * 16;

    const int ln15 = lane & 15, hb = (lane >> 4) * 16;
    u32 ahB = smem_u32(Ahs) + 2 * ((wr * 32 + ln15) * AST) + hb;
    u32 alB = smem_u32(Als) + 2 * ((wr * 32 + ln15) * AST) + hb;
    u32 bhB = smem_u32(Bhs) + 2 * (ln15 * BST + wc * 64) + hb;
    u32 blB = smem_u32(Bls) + 2 * (ln15 * BST + wc * 64) + hb;

    float acc[2][8][4];
#pragma unroll
    for (int i = 0; i < 2; i++)
#pragma unroll
        for (int j = 0; j < 8; j++)
#pragma unroll
            for (int k = 0; k < 4; k++) acc[i][j][k] = 0.f;

    // prefetch iter 0
    float4 af[4], bf[4];
    {
        const float4* ap4 = (const float4*)(edRow + kh);
        const float4* bp4 = (const float4*)(w1 + (size_t)bk * HID + bc);
#pragma unroll
        for (int j = 0; j < 4; j++) { af[j] = ap4[j]; bf[j] = bp4[j]; }
    }
    for (int k0 = 0; k0 < DIN; k0 += 32) {
        __syncthreads();
        stage_a16(Ahs, Als, r, kh, af);
        stage_b16(Bhs, Bls, bk, bc, bf);
        __syncthreads();
        if (k0 + 32 < DIN) {
            int kg = k0 + 32 + kh;
            const float* ap = (kg < BASIS) ? edRow + kg
                            : (kg < BASIS + HID) ? srcRow + (kg - BASIS)
                            : tgtRow + (kg - BASIS - HID);
            const float4* ap4 = (const float4*)ap;
            const float4* bp4 = (const float4*)(w1 + (size_t)(k0 + 32 + bk) * HID + bc);
#pragma unroll
            for (int j = 0; j < 4; j++) { af[j] = ap4[j]; bf[j] = bp4[j]; }
        }
        compute_iter(ahB, alB, bhB, blB, acc);
    }
    ln_epi_mma(acc, rowBase, wr, wc, lane, b1, g1, be1, g_h1, redS, redQ);
}

// ---------------- GEMM2: g_h1 @ w2 -> LN/SiLU -> g_h2 ----------------------
__global__ __launch_bounds__(256) void k_mgemm2(
    const float* __restrict__ w2, const float* __restrict__ b2,
    const float* __restrict__ g2, const float* __restrict__ be2)
{
    __shared__ __align__(16) u16 Ahs[128 * AST], Als[128 * AST];
    __shared__ __align__(16) u16 Bhs[32 * BST], Bls[32 * BST];
    __shared__ float redS[128 * 2], redQ[128 * 2];
    const int tid = threadIdx.x, lane = tid & 31, wid = tid >> 5;
    const int wr = wid >> 1, wc = wid & 1;
    const int rowBase = blockIdx.x * 128;
    const int r = tid >> 1, kh = (tid & 1) * 16;
    const int eRow = rowBase + r;
    const int bk = tid >> 3, bc = (tid & 7) * 16;

    const int ln15 = lane & 15, hb = (lane >> 4) * 16;
    u32 ahB = smem_u32(Ahs) + 2 * ((wr * 32 + ln15) * AST) + hb;
    u32 alB = smem_u32(Als) + 2 * ((wr * 32 + ln15) * AST) + hb;
    u32 bhB = smem_u32(Bhs) + 2 * (ln15 * BST + wc * 64) + hb;
    u32 blB = smem_u32(Bls) + 2 * (ln15 * BST + wc * 64) + hb;

    float acc[2][8][4];
#pragma unroll
    for (int i = 0; i < 2; i++)
#pragma unroll
        for (int j = 0; j < 8; j++)
#pragma unroll
            for (int k = 0; k < 4; k++) acc[i][j][k] = 0.f;

    float4 af[4], bf[4];
    {
        const float4* ap4 = (const float4*)(g_h1 + (size_t)eRow * HID + kh);
        const float4* bp4 = (const float4*)(w2 + (size_t)bk * HID + bc);
#pragma unroll
        for (int j = 0; j < 4; j++) { af[j] = ap4[j]; bf[j] = bp4[j]; }
    }
    for (int k0 = 0; k0 < HID; k0 += 32) {
        __syncthreads();
        stage_a16(Ahs, Als, r, kh, af);
        stage_b16(Bhs, Bls, bk, bc, bf);
        __syncthreads();
        if (k0 + 32 < HID) {
            const float4* ap4 = (const float4*)(g_h1 + (size_t)eRow * HID + k0 + 32 + kh);
            const float4* bp4 = (const float4*)(w2 + (size_t)(k0 + 32 + bk) * HID + bc);
#pragma unroll
            for (int j = 0; j < 4; j++) { af[j] = ap4[j]; bf[j] = bp4[j]; }
        }
        compute_iter(ahB, alB, bhB, blB, acc);
    }
    ln_epi_mma(acc, rowBase, wr, wc, lane, b2, g2, be2, g_h2, redS, redQ);
}

// ---------------- GEMM3: g_h2 @ w3 + b3 -> split bf16 x0 images ------------
__global__ __launch_bounds__(256) void k_mgemm3(
    const float* __restrict__ w3, const float* __restrict__ b3)
{
    __shared__ __align__(16) u16 Ahs[128 * AST], Als[128 * AST];
    __shared__ __align__(16) u16 Bhs[32 * BST], Bls[32 * BST];
    const int tid = threadIdx.x, lane = tid & 31, wid = tid >> 5;
    const int wr = wid >> 1, wc = wid & 1;
    const int rowBase = blockIdx.y * 128;
    const int nBase = blockIdx.x * 128;
    const int r = tid >> 1, kh = (tid & 1) * 16;
    const int eRow = rowBase + r;
    const int bk = tid >> 3, bc = (tid & 7) * 16;

    const int ln15 = lane & 15, hb = (lane >> 4) * 16;
    u32 ahB = smem_u32(Ahs) + 2 * ((wr * 32 + ln15) * AST) + hb;
    u32 alB = smem_u32(Als) + 2 * ((wr * 32 + ln15) * AST) + hb;
    u32 bhB = smem_u32(Bhs) + 2 * (ln15 * BST + wc * 64) + hb;
    u32 blB = smem_u32(Bls) + 2 * (ln15 * BST + wc * 64) + hb;

    float acc[2][8][4];
#pragma unroll
    for (int i = 0; i < 2; i++)
#pragma unroll
        for (int j = 0; j < 8; j++)
#pragma unroll
            for (int k = 0; k < 4; k++) acc[i][j][k] = 0.f;

    float4 af[4], bf[4];
    {
        const float4* ap4 = (const float4*)(g_h2 + (size_t)eRow * HID + kh);
        const float4* bp4 = (const float4*)(w3 + (size_t)bk * W3N + nBase + bc);
#pragma unroll
        for (int j = 0; j < 4; j++) { af[j] = ap4[j]; bf[j] = bp4[j]; }
    }
    for (int k0 = 0; k0 < HID; k0 += 32) {
        __syncthreads();
        stage_a16(Ahs, Als, r, kh, af);
        stage_b16(Bhs, Bls, bk, bc, bf);
        __syncthreads();
        if (k0 + 32 < HID) {
            const float4* ap4 = (const float4*)(g_h2 + (size_t)eRow * HID + k0 + 32 + kh);
            const float4* bp4 = (const float4*)(w3 + (size_t)(k0 + 32 + bk) * W3N + nBase + bc);
#pragma unroll
            for (int j = 0; j < 4; j++) { af[j] = ap4[j]; bf[j] = bp4[j]; }
        }
        compute_iter(ahB, alB, bhB, blB, acc);
    }
    // bias epilogue, split-bf16 store
    int gid = lane >> 2, q = lane & 3;
#pragma unroll
    for (int mt = 0; mt < 2; mt++)
#pragma unroll
        for (int sub = 0; sub < 2; sub++) {
            int rl = wr * 32 + mt * 16 + sub * 8 + gid;
            size_t rbase = (size_t)(rowBase + rl) * W3N + nBase;
#pragma unroll
            for (int nt = 0; nt < 8; nt++) {
                int col = wc * 64 + nt * 8 + q * 2;
                float v0 = acc[mt][nt][sub * 2] + b3[nBase + col];
                float v1 = acc[mt][nt][sub * 2 + 1] + b3[nBase + col + 1];
                u32 hi, lo;
                split2(v0, v1, hi, lo);
                *(u32*)&g_x0h[rbase + col] = hi;
                *(u32*)&g_x0l[rbase + col] = lo;
            }
        }
}

// ---------------- per-node rotate + reduce via mma ---------------------------
// acc[n-tile] accumulates over ALL edges of the node in registers.
// A = gathered wigner (64x16, rows>=49 & cols>=7 zero), B = x0 (16x128, rows>=7 zero-once)
__global__ __launch_bounds__(256) void k_node(
    const float* __restrict__ wig, float* __restrict__ out)
{
    __shared__ __align__(16) u16 Ah[64 * ASTN], Al[64 * ASTN];
    __shared__ __align__(16) u16 Bh[16 * BSTN], Bl[16 * BSTN];
    const int tid = threadIdx.x, lane = tid & 31, wid = tid >> 5;
    const int wr = wid >> 1, wc = wid & 1;
    const int n = blockIdx.x;

    // zero pads once
    for (int i = tid; i < 64 * ASTN; i += 256) { Ah[i] = 0; Al[i] = 0; }
    for (int i = tid; i < 16 * BSTN; i += 256) { Bh[i] = 0; Bl[i] = 0; }

    const int gi0 = tid, gi1 = tid + 256;
    const int widx0 = g_wigidx[gi0 < NGATH ? gi0 : 0];
    const int dsti0 = g_dstidx[gi0 < NGATH ? gi0 : 0];
    const int widx1 = (gi1 < NGATH) ? g_wigidx[gi1] : 0;
    const int dsti1 = (gi1 < NGATH) ? g_dstidx[gi1] : 0;

    const int beg = g_off[n];
    const int end = g_off[n + 1];

    const int ln15 = lane & 15, hbb = (lane >> 4) * 16;
    u32 aA  = smem_u32(Ah) + 2 * ((wr * 16 + ln15) * ASTN) + hbb;
    u32 aAl = smem_u32(Al) + 2 * ((wr * 16 + ln15) * ASTN) + hbb;
    u32 aB  = smem_u32(Bh) + 2 * (ln15 * BSTN + wc * 64) + hbb;
    u32 aBl = smem_u32(Bl) + 2 * (ln15 * BSTN + wc * 64) + hbb;

    float acc[8][4];
#pragma unroll
    for (int j = 0; j < 8; j++)
#pragma unroll
        for (int k = 0; k < 4; k++) acc[j][k] = 0.f;

    __syncthreads();

    for (int ii = beg; ii < end; ii++) {
        int e = g_edges[ii];
        const float* wp = wig + (size_t)e * WROW;
        if (gi0 < NGATH) {
            u16 h, l; split1(wp[widx0], h, l);
            Ah[dsti0] = h; Al[dsti0] = l;
        }
        if (gi1 < NGATH) {
            u16 h, l; split1(wp[widx1], h, l);
            Ah[dsti1] = h; Al[dsti1] = l;
        }
        // x0 images: 112 uint4 per buffer (7 rows x 128 cols bf16)
        if (tid < 112) {
            int m = tid >> 4, c = (tid & 15) << 3;
            *(uint4*)&Bh[m * BSTN + c] =
                ((const uint4*)g_x0h)[(size_t)e * 112 + tid];
        } else if (tid >= 128 && tid < 240) {
            int t = tid - 128;
            int m = t >> 4, c = (t & 15) << 3;
            *(uint4*)&Bl[m * BSTN + c] =
                ((const uint4*)g_x0l)[(size_t)e * 112 + t];
        }
        __syncthreads();

        u32 ah[4], al4[4];
        LDSM4(ah[0], ah[1], ah[2], ah[3], aA);
        LDSM4(al4[0], al4[1], al4[2], al4[3], aAl);
        u32 bh[4][4], bl[4][4];
#pragma unroll
        for (int p = 0; p < 4; p++) {
            LDSM4T(bh[p][0], bh[p][1], bh[p][2], bh[p][3], aB + p * 32);
            LDSM4T(bl[p][0], bl[p][1], bl[p][2], bl[p][3], aBl + p * 32);
        }
#pragma unroll
        for (int p = 0; p < 4; p++)
#pragma unroll
            for (int h = 0; h < 2; h++) {
                int nt = p * 2 + h;
                MMA_BF16(acc[nt], ah[0], ah[1], ah[2], ah[3],
                         bh[p][h * 2], bh[p][h * 2 + 1]);
                MMA_BF16(acc[nt], ah[0], ah[1], ah[2], ah[3],
                         bl[p][h * 2], bl[p][h * 2 + 1]);
                MMA_BF16(acc[nt], al4[0], al4[1], al4[2], al4[3],
                         bh[p][h * 2], bh[p][h * 2 + 1]);
            }
        __syncthreads();
    }

    const float sc = (float)(1.0 / 23.395238876342773);
    int gid = lane >> 2, q = lane & 3;
#pragma unroll
    for (int sub = 0; sub < 2; sub++) {
        int rr = wr * 16 + sub * 8 + gid;
        if (rr < NSPH) {
            float* op = out + (size_t)n * (NSPH * CCH) + rr * CCH;
#pragma unroll
            for (int nt = 0; nt < 8; nt++) {
                int col = wc * 64 + nt * 8 + q * 2;
                *(float2*)(op + col) = make_float2(acc[nt][sub * 2] * sc,
                                                   acc[nt][sub * 2 + 1] * sc);
            }
        }
    }
}

// ---------------- launch ----------------
extern "C" void kernel_launch(void* const* d_in, const int* in_sizes, int n_in,
                              void* d_out, int out_size)
{
    const int*   an   = (const int*)d_in[0];
    const float* ed   = (const float*)d_in[1];
    const int*   eidx = (const int*)d_in[2];
    const float* srcT = (const float*)d_in[3];
    const float* tgtT = (const float*)d_in[4];
    const float* w1   = (const float*)d_in[5];
    const float* b1   = (const float*)d_in[6];
    const float* g1   = (const float*)d_in[7];
    const float* be1  = (const float*)d_in[8];
    const float* w2   = (const float*)d_in[9];
    const float* b2   = (const float*)d_in[10];
    const float* g2   = (const float*)d_in[11];
    const float* be2  = (const float*)d_in[12];
    const float* w3   = (const float*)d_in[13];
    const float* b3   = (const float*)d_in[14];
    const float* tom  = (const float*)d_in[15];
    const float* wig  = (const float*)d_in[16];
    float* out = (float*)d_out;

    k_zero<<<(NODES + 255) / 256, 256>>>();
    k_hist<<<(E_NUM + 255) / 256, 256>>>(eidx);
    k_prep<<<1, 256>>>(tom);
    k_scatter<<<(E_NUM + 255) / 256, 256>>>(eidx);
    k_mgemm1<<<E_NUM / 128, 256>>>(an, ed, eidx, srcT, tgtT, w1, b1, g1, be1);
    k_mgemm2<<<E_NUM / 128, 256>>>(w2, b2, g2, be2);
    k_mgemm3<<<dim3(W3N / 128, E_NUM / 128), 256>>>(w3, b3);
    k_node<<<NODES, 256>>>(wig, out);
}